// round 15
// baseline (speedup 1.0000x reference)
#include <cuda_runtime.h>
#include <cuda_bf16.h>
#include <cstdint>

// Problem constants
#define BB  4
#define SS  2048
#define DDm 1024
#define HHn 16
#define DKk 64
#define BSr (BB*SS)     // 8192 rows
#define N3  3072        // concat of Q|K|V projection outputs
#define BHh (BB*HHn)    // 64 head-batches

// ------------------------- scratch (static device memory) -------------------
__device__ uint32_t g_Bb [(size_t)N3 * 512];          // B bf16x2 [j][d-words], word-scrambled
__device__ uint32_t g_Xb [(size_t)BSr * 512];         // x bf16x2 [r][d-words], word-scrambled
__device__ uint32_t g_INb[(size_t)BSr * 1536];        // projections bf16x2 [r][j-words]
__device__ float    g_lam[BSr];                       // per-row lambda
__device__ float4   g_par[2048];                      // per-col {2*zn, cosh2r, sinh2r, 0}
__device__ uint32_t g_Qb [(size_t)BHh * SS * 32];     // Q bf16x2 [bh][s][dk-words], scale 1/8
__device__ uint32_t g_Kb [(size_t)BHh * SS * 32];     // K bf16x2 word-scrambled
__device__ uint32_t g_Vb [(size_t)BHh * DKk * 1024];  // V bf16x2 [bh][dk][s-words] word-scrambled
__device__ float    g_cs4[4 * BHh * DKk];             // partial colsums of V projection

// ------------------------- helpers ------------------------------------------
__device__ __forceinline__ uint32_t pkbf(float lo, float hi) {
    uint32_t d; asm("cvt.rn.bf16x2.f32 %0, %1, %2;" : "=r"(d) : "f"(hi), "f"(lo)); return d;
}
__device__ __forceinline__ float2 upbf(uint32_t w) {
    return make_float2(__uint_as_float(w << 16), __uint_as_float(w & 0xffff0000u));
}
// centered softmax numerator: q = e^y - 1, |y| <= 0.13, quartic Taylor (FMA pipe only)
__device__ __forceinline__ float em1(float y) {
    return y * fmaf(y, fmaf(y, fmaf(y, 0.041666668f, 0.16666667f), 0.5f), 1.0f);
}
// word scramble within an 8-word block: phys = 2*(w&3) + ((w>>2)&1)
__device__ __forceinline__ uint32_t ph(uint32_t w) {
    return (w & ~7u) + 2u * (w & 3u) + ((w >> 2) & 1u);
}
__device__ __forceinline__ void mma_bf16(float c[4], const uint32_t a[4],
                                         uint32_t b0, uint32_t b1) {
    asm volatile(
        "mma.sync.aligned.m16n8k16.row.col.f32.bf16.bf16.f32 "
        "{%0,%1,%2,%3}, {%4,%5,%6,%7}, {%8,%9}, {%0,%1,%2,%3};\n"
        : "+f"(c[0]), "+f"(c[1]), "+f"(c[2]), "+f"(c[3])
        : "r"(a[0]), "r"(a[1]), "r"(a[2]), "r"(a[3]), "r"(b0), "r"(b1));
}
__device__ __forceinline__ void cpasync16(uint32_t saddr, const void* gptr) {
    asm volatile("cp.async.cg.shared.global [%0], [%1], 16;\n"
                 :: "r"(saddr), "l"(gptr) : "memory");
}
#define CP_COMMIT() asm volatile("cp.async.commit_group;\n" ::: "memory")
#define CP_WAIT2()  asm volatile("cp.async.wait_group 2;\n" ::: "memory")
#define CP_WAIT1()  asm volatile("cp.async.wait_group 1;\n" ::: "memory")
#define CP_WAIT0()  asm volatile("cp.async.wait_group 0;\n" ::: "memory")

// ------------------------- block reduction helpers --------------------------
__device__ __forceinline__ float bcastSum(float v) {
    __shared__ float sm[8];
    #pragma unroll
    for (int m = 16; m > 0; m >>= 1) v += __shfl_xor_sync(0xffffffffu, v, m);
    int w = threadIdx.x >> 5;
    if ((threadIdx.x & 31) == 0) sm[w] = v;
    __syncthreads();
    if (threadIdx.x < 8) {
        v = sm[threadIdx.x];
        #pragma unroll
        for (int m = 4; m > 0; m >>= 1) v += __shfl_xor_sync(0x000000ffu, v, m);
        if (threadIdx.x == 0) sm[0] = v;
    }
    __syncthreads();
    v = sm[0];
    __syncthreads();
    return v;
}

__device__ __forceinline__ void bcastSum4(float v[4]) {
    __shared__ float sm4[8][4];
    #pragma unroll
    for (int m = 16; m > 0; m >>= 1) {
        #pragma unroll
        for (int c = 0; c < 4; c++) v[c] += __shfl_xor_sync(0xffffffffu, v[c], m);
    }
    int w = threadIdx.x >> 5;
    if ((threadIdx.x & 31) == 0) {
        #pragma unroll
        for (int c = 0; c < 4; c++) sm4[w][c] = v[c];
    }
    __syncthreads();
    if (threadIdx.x < 8) {
        #pragma unroll
        for (int c = 0; c < 4; c++) v[c] = sm4[threadIdx.x][c];
        #pragma unroll
        for (int m = 4; m > 0; m >>= 1) {
            #pragma unroll
            for (int c = 0; c < 4; c++) v[c] += __shfl_xor_sync(0x000000ffu, v[c], m);
        }
        if (threadIdx.x == 0) {
            #pragma unroll
            for (int c = 0; c < 4; c++) sm4[0][c] = v[c];
        }
    }
    __syncthreads();
    #pragma unroll
    for (int c = 0; c < 4; c++) v[c] = sm4[0][c];
    __syncthreads();
}

// ------------------------- prep: bf16-scrambled B + per-col params ----------
__global__ __launch_bounds__(256) void prep_kernel(
    const float* __restrict__ zq, const float* __restrict__ bq,
    const float* __restrict__ zk, const float* __restrict__ bk,
    const float* __restrict__ wv)
{
    int j = blockIdx.x;
    int tid = threadIdx.x;
    int d0 = tid * 4;
    uint32_t w0 = tid * 2;
    if (j >= 2048) {
        int col = j - 2048;
        float4 v = *(const float4*)(wv + (size_t)col * DDm + d0);
        uint32_t* row = g_Bb + (size_t)j * 512;
        row[ph(w0)]     = pkbf(v.x, v.y);
        row[ph(w0 + 1)] = pkbf(v.z, v.w);
        return;
    }
    const float* z; const float* bias; int col;
    if (j < 1024) { z = zq; bias = bq; col = j; }
    else          { z = zk; bias = bk; col = j - 1024; }

    float vv[4];
    #pragma unroll
    for (int c = 0; c < 4; c++) vv[c] = z[(size_t)(d0 + c) * DDm + col];
    float ss = vv[0] * vv[0] + vv[1] * vv[1] + vv[2] * vv[2] + vv[3] * vv[3];
    ss = bcastSum(ss);
    float zn = fmaxf(sqrtf(ss), 1e-15f);
    float inv = 1.0f / zn;
    uint32_t* row = g_Bb + (size_t)j * 512;
    row[ph(w0)]     = pkbf(vv[0] * inv, vv[1] * inv);
    row[ph(w0 + 1)] = pkbf(vv[2] * inv, vv[3] * inv);
    if (tid == 0) {
        float r2 = 2.0f * bias[col];
        g_par[j] = make_float4(2.0f * zn, coshf(r2), sinhf(r2), 0.0f);
    }
}

// ------------- lambda + bf16-scrambled x (single pass over x) ---------------
__global__ __launch_bounds__(256) void lam_kernel(const float* __restrict__ x) {
    int r = blockIdx.x;
    int t = threadIdx.x;
    float4 v = *(const float4*)(x + (size_t)r * DDm + t * 4);
    float ss = v.x * v.x + v.y * v.y + v.z * v.z + v.w * v.w;
    uint32_t* row = g_Xb + (size_t)r * 512;
    uint32_t w0 = t * 2;
    row[ph(w0)]     = pkbf(v.x, v.y);
    row[ph(w0 + 1)] = pkbf(v.z, v.w);
    ss = bcastSum(ss);
    if (t == 0) g_lam[r] = 2.0f / (1.0f - ss);
}

// ------------------------- bf16 GEMM: g_INb = x @ B (m16n8k16) --------------
#define GAT 5120                          // words per [128][40] tile
__global__ __launch_bounds__(256, 2) void gemm_bf() {
    extern __shared__ uint32_t sm[];
    uint32_t sbase = (uint32_t)__cvta_generic_to_shared(sm);

    int tid = threadIdx.x;
    int warp = tid >> 5, lane = tid & 31;
    int g = lane >> 2, tig = lane & 3;
    int wm = warp >> 2, wn = warp & 3;
    int m0 = blockIdx.y * 128, n0 = blockIdx.x * 128;

    const uint32_t* Aw = g_Xb + (size_t)m0 * 512;
    const uint32_t* Bw = g_Bb + (size_t)n0 * 512;

    auto load_chunk = [&](int ch, int buf) {
        uint32_t dst = sbase + (uint32_t)(buf * 2 * GAT) * 4;
        #pragma unroll
        for (int i = 0; i < 8; i++) {
            int id = tid + i * 256;            // 0..2047
            int mat = id >> 10;                // 0:A 1:B
            int r = (id & 1023) >> 3;
            int o4 = (id & 7) * 4;
            uint32_t s = dst + (uint32_t)(mat * GAT + r * 40 + o4) * 4;
            const uint32_t* gp = (mat ? Bw : Aw) + (size_t)r * 512 + ch * 32 + o4;
            cpasync16(s, gp);
        }
        CP_COMMIT();
    };

    float acc[4][4][4];
    #pragma unroll
    for (int mi = 0; mi < 4; mi++)
        #pragma unroll
        for (int ni = 0; ni < 4; ni++)
            #pragma unroll
            for (int c = 0; c < 4; c++) acc[mi][ni][c] = 0.0f;

    load_chunk(0, 0);

    int buf = 0;
    for (int ch = 0; ch < 16; ch++) {
        if (ch + 1 < 16) {
            load_chunk(ch + 1, buf ^ 1);
            CP_WAIT1();
        } else {
            CP_WAIT0();
        }
        __syncthreads();
        const uint32_t* A = sm + buf * 2 * GAT;
        const uint32_t* B = A + GAT;

        #pragma unroll
        for (int ks = 0; ks < 4; ks++) {
            uint32_t af[4][4];
            #pragma unroll
            for (int mi = 0; mi < 4; mi++) {
                int r = wm * 64 + mi * 16;
                uint2 v = *(const uint2*)&A[(r + g)     * 40 + ks * 8 + 2 * tig];
                uint2 u = *(const uint2*)&A[(r + g + 8) * 40 + ks * 8 + 2 * tig];
                af[mi][0] = v.x; af[mi][1] = u.x; af[mi][2] = v.y; af[mi][3] = u.y;
            }
            uint2 bfv[4];
            #pragma unroll
            for (int ni = 0; ni < 4; ni++)
                bfv[ni] = *(const uint2*)&B[(wn * 32 + ni * 8 + g) * 40 + ks * 8 + 2 * tig];
            #pragma unroll
            for (int mi = 0; mi < 4; mi++)
                #pragma unroll
                for (int ni = 0; ni < 4; ni++)
                    mma_bf16(acc[mi][ni], af[mi], bfv[ni].x, bfv[ni].y);
        }
        __syncthreads();
        buf ^= 1;
    }

    // epilogue: pack fp32 accumulators to bf16x2 words
    #pragma unroll
    for (int mi = 0; mi < 4; mi++) {
        int mr = m0 + wm * 64 + mi * 16 + g;
        #pragma unroll
        for (int ni = 0; ni < 4; ni++) {
            int wc = (n0 + wn * 32 + ni * 8 + tig * 2) >> 1;
            g_INb[(size_t)mr * 1536 + wc]       = pkbf(acc[mi][ni][0], acc[mi][ni][1]);
            g_INb[(size_t)(mr + 8) * 1536 + wc] = pkbf(acc[mi][ni][2], acc[mi][ni][3]);
        }
    }
}

// ------------------------- colsum of V projection (packed reads) ------------
__global__ __launch_bounds__(256) void csum_kernel() {
    int bh = blockIdx.x;
    int c  = blockIdx.y;
    int b = bh >> 4, h = bh & 15;
    int t = threadIdx.x;
    int w = t & 31, sub = t >> 5;            // sub 0..7
    int srow0 = c * 512 + sub * 64;
    const uint32_t* base = g_INb + ((size_t)(b * 2048 + srow0)) * 1536 + 1024 + h * 32 + w;
    float sl = 0.f, sh = 0.f;
    for (int i = 0; i < 64; i++) {
        float2 v = upbf(base[(size_t)i * 1536]);
        sl += v.x; sh += v.y;
    }
    __shared__ float red[256][2];
    red[t][0] = sl; red[t][1] = sh;
    __syncthreads();
    if (t < 32) {
        float al = 0.f, ah = 0.f;
        #pragma unroll
        for (int s = 0; s < 8; s++) {
            al += red[s * 32 + t][0];
            ah += red[s * 32 + t][1];
        }
        g_cs4[(c * BHh + bh) * 64 + 2 * t]     = al;
        g_cs4[(c * BHh + bh) * 64 + 2 * t + 1] = ah;
    }
}

// ------------------------- epilogue: Poincare map -> bf16 layouts -----------
__global__ __launch_bounds__(256) void epi_kernel(const float* __restrict__ bvp) {
    int r0 = blockIdx.x * 4;
    int b  = r0 >> 11;
    int s0 = r0 & 2047;
    int tid = threadIdx.x;
    int j0 = tid * 4;
    int h  = j0 >> 6, dk = j0 & 63;
    int bh = b * 16 + h;

    float lamv[4];
    *(float4*)lamv = *(const float4*)(g_lam + r0);

    float wq[4][4];
    // ---------------- Q (scaled 1/8: natural-log scores) ----------------
    {
        float4 par[4];
        #pragma unroll
        for (int c = 0; c < 4; c++) par[c] = g_par[j0 + c];
        float ws[4] = {0.f, 0.f, 0.f, 0.f};
        #pragma unroll
        for (int ri = 0; ri < 4; ri++) {
            float lam = lamv[ri], lm1 = lam - 1.0f;
            uint2 iw = *(const uint2*)(g_INb + (size_t)(r0 + ri) * 1536 + tid * 2);
            float2 i0 = upbf(iw.x), i1 = upbf(iw.y);
            float innv[4] = {i0.x, i0.y, i1.x, i1.y};
            #pragma unroll
            for (int c = 0; c < 4; c++) {
                float arg = lam * innv[c] * par[c].y - lm1 * par[c].z;
                float t   = arg + sqrtf(arg * arg + 1.0f);
                float u   = par[c].x * __logf(t);
                float eu  = __expf(u);
                float w   = 0.5f * (eu - __fdividef(1.0f, eu));
                wq[ri][c] = w;
                ws[ri] += w * w;
            }
        }
        bcastSum4(ws);
        #pragma unroll
        for (int ri = 0; ri < 4; ri++) {
            float scl = 0.125f / (1.0f + sqrtf(1.0f + ws[ri]));
            uint2 ov = make_uint2(pkbf(wq[ri][0] * scl, wq[ri][1] * scl),
                                  pkbf(wq[ri][2] * scl, wq[ri][3] * scl));
            *(uint2*)(g_Qb + ((size_t)bh * SS + s0 + ri) * 32 + (dk >> 1)) = ov;
        }
    }
    // ---------------- K (word-scrambled dk layout) ----------------
    {
        float4 par[4];
        #pragma unroll
        for (int c = 0; c < 4; c++) par[c] = g_par[1024 + j0 + c];
        float ws2[4] = {0.f, 0.f, 0.f, 0.f};
        #pragma unroll
        for (int ri = 0; ri < 4; ri++) {
            float lam = lamv[ri], lm1 = lam - 1.0f;
            uint2 iw = *(const uint2*)(g_INb + (size_t)(r0 + ri) * 1536 + 512 + tid * 2);
            float2 i0 = upbf(iw.x), i1 = upbf(iw.y);
            float innv[4] = {i0.x, i0.y, i1.x, i1.y};
            #pragma unroll
            for (int c = 0; c < 4; c++) {
                float arg = lam * innv[c] * par[c].y - lm1 * par[c].z;
                float t   = arg + sqrtf(arg * arg + 1.0f);
                float u   = par[c].x * __logf(t);
                float eu  = __expf(u);
                float w   = 0.5f * (eu - __fdividef(1.0f, eu));
                wq[ri][c] = w;
                ws2[ri] += w * w;
            }
        }
        bcastSum4(ws2);
        uint32_t wl0 = dk >> 1;
        uint32_t p0 = ph(wl0), p1 = ph(wl0 + 1);
        #pragma unroll
        for (int ri = 0; ri < 4; ri++) {
            float scl = 1.0f / (1.0f + sqrtf(1.0f + ws2[ri]));
            uint32_t* row = g_Kb + ((size_t)bh * SS + s0 + ri) * 32;
            row[p0] = pkbf(wq[ri][0] * scl, wq[ri][1] * scl);
            row[p1] = pkbf(wq[ri][2] * scl, wq[ri][3] * scl);
        }
    }
    // ---------------- V (transposed, word-scrambled s layout) ----------------
    {
        float4 bvv = *(const float4*)(bvp + j0);
        float vv[4][4];
        #pragma unroll
        for (int ri = 0; ri < 4; ri++) {
            uint2 iw = *(const uint2*)(g_INb + (size_t)(r0 + ri) * 1536 + 1024 + tid * 2);
            float2 i0 = upbf(iw.x), i1 = upbf(iw.y);
            vv[ri][0] = i0.x + bvv.x;
            vv[ri][1] = i0.y + bvv.y;
            vv[ri][2] = i1.x + bvv.z;
            vv[ri][3] = i1.y + bvv.w;
        }
        uint32_t wl0 = s0 >> 1;
        uint32_t ps0 = ph(wl0), ps1 = ph(wl0 + 1);
        #pragma unroll
        for (int c = 0; c < 4; c++) {
            uint32_t* row = g_Vb + ((size_t)bh * DKk + dk + c) * 1024;
            row[ps0] = pkbf(vv[0][c], vv[1][c]);
            row[ps1] = pkbf(vv[2][c], vv[3][c]);
        }
    }
}

// --------- flash attention (bf16, polynomial centered softmax, 3-stage) -----
// O = colsumV + sum_k q_k v_k with q = e^y - 1 (quartic Taylor, FMA-only);
// l = 2048 + sum q. No MUFU, no max, no rescaling.
__global__ __launch_bounds__(256, 2) void attn_kernel(float* __restrict__ out,
                                                      const float* __restrict__ bvp) {
    extern __shared__ uint32_t usmem[];
    const int TW = 64 * 40;                  // 2560 words per tile
    uint32_t sbase = (uint32_t)__cvta_generic_to_shared(usmem);

    int tid  = threadIdx.x;
    int warp = tid >> 5, lane = tid & 31;
    int g = lane >> 2, tig = lane & 3;
    int bh = blockIdx.y;
    int b  = bh >> 4, h = bh & 15;
    int q0 = blockIdx.x * 128;
    int wq = warp * 16;

    const uint32_t* Qw = g_Qb + ((size_t)bh * SS + q0 + wq) * 32;
    const uint32_t* Kw = g_Kb + (size_t)bh * SS * 32;
    const uint32_t* Vw = g_Vb + (size_t)bh * DKk * 1024;

    uint32_t qa[4][4];
    #pragma unroll
    for (int ktq = 0; ktq < 4; ktq++) {
        qa[ktq][0] = Qw[(size_t)g       * 32 + ktq * 8 + tig];
        qa[ktq][1] = Qw[(size_t)(g + 8) * 32 + ktq * 8 + tig];
        qa[ktq][2] = Qw[(size_t)g       * 32 + ktq * 8 + tig + 4];
        qa[ktq][3] = Qw[(size_t)(g + 8) * 32 + ktq * 8 + tig + 4];
    }

    float o[8][4];
    #pragma unroll
    for (int n = 0; n < 8; n++)
        #pragma unroll
        for (int c = 0; c < 4; c++) o[n][c] = 0.0f;
    float l0 = 0.0f, l1 = 0.0f;          // centered sums: l = 2048 + l0

    auto load_tile = [&](int buf3, int it) {
        int kc0 = it * 64;
        uint32_t sk = sbase + (uint32_t)(buf3 * TW) * 4;
        uint32_t sv = sbase + (uint32_t)((3 + buf3) * TW) * 4;
        #pragma unroll
        for (int i = 0; i < 2; i++) {
            int chunk = tid + i * 256;
            int row = chunk >> 3;
            int off = (chunk & 7) * 4;
            cpasync16(sk + (uint32_t)(row * 40 + off) * 4,
                      Kw + (size_t)(kc0 + row) * 32 + off);
            cpasync16(sv + (uint32_t)(row * 40 + off) * 4,
                      Vw + (size_t)row * 1024 + it * 32 + off);
        }
        CP_COMMIT();
    };

    load_tile(0, 0);
    load_tile(1, 1);

    for (int it = 0; it < SS / 64; it++) {
        int cur = it % 3;
        if (it + 2 < SS / 64) {
            load_tile((it + 2) % 3, it + 2);
            CP_WAIT2();
        } else if (it + 1 < SS / 64) {
            CP_WAIT1();
        } else {
            CP_WAIT0();
        }
        __syncthreads();
        const uint32_t* sK = usmem + cur * TW;
        const uint32_t* sV = usmem + (3 + cur) * TW;

        float p[8][4];
        #pragma unroll
        for (int n = 0; n < 8; n++)
            #pragma unroll
            for (int c = 0; c < 4; c++) p[n][c] = 0.0f;
        #pragma unroll
        for (int ktq = 0; ktq < 4; ktq++) {
            #pragma unroll
            for (int n0 = 0; n0 < 8; n0++) {
                uint2 kb = *(const uint2*)(sK + (n0 * 8 + g) * 40 + ktq * 8 + 2 * tig);
                mma_bf16(p[n0], qa[ktq], kb.x, kb.y);
            }
        }

        // q = e^y - 1 via quartic Taylor (|y| <= 0.13); accumulate centered sums
        #pragma unroll
        for (int n = 0; n < 8; n++) {
            float q0v = em1(p[n][0]);
            float q1v = em1(p[n][1]);
            float q2v = em1(p[n][2]);
            float q3v = em1(p[n][3]);
            l0 += q0v + q1v;
            l1 += q2v + q3v;
            p[n][0] = q0v; p[n][1] = q1v; p[n][2] = q2v; p[n][3] = q3v;
        }

        uint32_t pa[4][4];
        #pragma unroll
        for (int ktp = 0; ktp < 4; ktp++) {
            pa[ktp][0] = pkbf(p[2 * ktp    ][0], p[2 * ktp    ][1]);
            pa[ktp][1] = pkbf(p[2 * ktp    ][2], p[2 * ktp    ][3]);
            pa[ktp][2] = pkbf(p[2 * ktp + 1][0], p[2 * ktp + 1][1]);
            pa[ktp][3] = pkbf(p[2 * ktp + 1][2], p[2 * ktp + 1][3]);
        }

        #pragma unroll
        for (int ktp = 0; ktp < 4; ktp++) {
            #pragma unroll
            for (int n0 = 0; n0 < 8; n0++) {
                uint2 vb = *(const uint2*)(sV + (n0 * 8 + g) * 40 + ktp * 8 + 2 * tig);
                mma_bf16(o[n0], pa[ktp], vb.x, vb.y);
            }
        }
        __syncthreads();
    }

    l0 += __shfl_xor_sync(0xffffffffu, l0, 1);
    l0 += __shfl_xor_sync(0xffffffffu, l0, 2);
    l1 += __shfl_xor_sync(0xffffffffu, l1, 1);
    l1 += __shfl_xor_sync(0xffffffffu, l1, 2);

    float inv0 = 1.0f / (2048.0f + l0);
    float inv1 = 1.0f / (2048.0f + l1);
    int s0r = q0 + wq + g;
    #pragma unroll
    for (int n0 = 0; n0 < 8; n0++) {
        int dk = n0 * 8 + 2 * tig;
        float csx = 0.0f, csy = 0.0f;
        #pragma unroll
        for (int c = 0; c < 4; c++) {
            float2 t = *(const float2*)(g_cs4 + ((size_t)(c * BHh + bh)) * 64 + dk);
            csx += t.x; csy += t.y;
        }
        float2 bv2 = *(const float2*)(bvp + h * 64 + dk);
        csx += 2048.0f * bv2.x;
        csy += 2048.0f * bv2.y;
        float2 ov0 = make_float2((csx + o[n0][0]) * inv0, (csy + o[n0][1]) * inv0);
        float2 ov1 = make_float2((csx + o[n0][2]) * inv1, (csy + o[n0][3]) * inv1);
        *(float2*)(out + ((size_t)(b * SS + s0r)     ) * DDm + h * 64 + dk) = ov0;
        *(float2*)(out + ((size_t)(b * SS + s0r + 8) ) * DDm + h * 64 + dk) = ov1;
    }
}

// ------------------------- launcher ----------------------------------------
extern "C" void kernel_launch(void* const* d_in, const int* in_sizes, int n_in,
                              void* d_out, int out_size) {
    const float* x  = (const float*)d_in[0];
    const float* zq = (const float*)d_in[1];
    const float* bq = (const float*)d_in[2];
    const float* zk = (const float*)d_in[3];
    const float* bk = (const float*)d_in[4];
    const float* wv = (const float*)d_in[5];
    const float* bv = (const float*)d_in[6];
    float* out = (float*)d_out;

    prep_kernel<<<N3, 256>>>(zq, bq, zk, bk, wv);
    lam_kernel<<<BSr, 256>>>(x);

    int gsmem = 2 * 2 * GAT * 4;   // 81920
    cudaFuncSetAttribute(gemm_bf, cudaFuncAttributeMaxDynamicSharedMemorySize, gsmem);
    gemm_bf<<<dim3(N3 / 128, BSr / 128), 256, gsmem>>>();

    csum_kernel<<<dim3(BHh, 4), 256>>>();
    epi_kernel<<<BSr / 4, 256>>>(bv);

    int smem_bytes = 6 * 64 * 40 * 4;   // 61440 (3-stage)
    cudaFuncSetAttribute(attn_kernel, cudaFuncAttributeMaxDynamicSharedMemorySize, smem_bytes);
    attn_kernel<<<dim3(SS / 128, BHh), 256, smem_bytes>>>(out, bv);
}

// round 16
// speedup vs baseline: 1.0563x; 1.0563x over previous
#include <cuda_runtime.h>
#include <cuda_bf16.h>
#include <cstdint>

// Problem constants
#define BB  4
#define SS  2048
#define DDm 1024
#define HHn 16
#define DKk 64
#define BSr (BB*SS)     // 8192 rows
#define N3  3072        // concat of Q|K|V projection outputs
#define BHh (BB*HHn)    // 64 head-batches

// ------------------------- scratch (static device memory) -------------------
__device__ uint32_t g_Bb [(size_t)N3 * 512];          // B bf16x2 [j][d-words], word-scrambled
__device__ uint32_t g_Xb [(size_t)BSr * 512];         // x bf16x2 [r][d-words], word-scrambled
__device__ uint32_t g_INb[(size_t)BSr * 1536];        // projections bf16x2 [r][j-words]
__device__ float    g_lam[BSr];                       // per-row lambda
__device__ float4   g_par[2048];                      // per-col {2*zn, cosh2r, sinh2r, 0}
__device__ uint32_t g_Qb [(size_t)BHh * SS * 32];     // Q bf16x2 [bh][s][dk-words], scale log2e/8
__device__ uint32_t g_Kb [(size_t)BHh * SS * 32];     // K bf16x2 word-scrambled
__device__ uint32_t g_Vb [(size_t)BHh * DKk * 1024];  // V bf16x2 [bh][dk][s-words] word-scrambled
__device__ float    g_cs4[4 * BHh * DKk];             // partial colsums of V projection

// ------------------------- helpers ------------------------------------------
__device__ __forceinline__ uint32_t pkbf(float lo, float hi) {
    uint32_t d; asm("cvt.rn.bf16x2.f32 %0, %1, %2;" : "=r"(d) : "f"(hi), "f"(lo)); return d;
}
__device__ __forceinline__ float2 upbf(uint32_t w) {
    return make_float2(__uint_as_float(w << 16), __uint_as_float(w & 0xffff0000u));
}
__device__ __forceinline__ float fex2(float x) {
    float r; asm("ex2.approx.ftz.f32 %0, %1;" : "=f"(r) : "f"(x)); return r;
}
// word scramble within an 8-word block: phys = 2*(w&3) + ((w>>2)&1)
__device__ __forceinline__ uint32_t ph(uint32_t w) {
    return (w & ~7u) + 2u * (w & 3u) + ((w >> 2) & 1u);
}
__device__ __forceinline__ void mma_bf16(float c[4], const uint32_t a[4],
                                         uint32_t b0, uint32_t b1) {
    asm volatile(
        "mma.sync.aligned.m16n8k16.row.col.f32.bf16.bf16.f32 "
        "{%0,%1,%2,%3}, {%4,%5,%6,%7}, {%8,%9}, {%0,%1,%2,%3};\n"
        : "+f"(c[0]), "+f"(c[1]), "+f"(c[2]), "+f"(c[3])
        : "r"(a[0]), "r"(a[1]), "r"(a[2]), "r"(a[3]), "r"(b0), "r"(b1));
}
__device__ __forceinline__ void cpasync16(uint32_t saddr, const void* gptr) {
    asm volatile("cp.async.cg.shared.global [%0], [%1], 16;\n"
                 :: "r"(saddr), "l"(gptr) : "memory");
}
#define CP_COMMIT() asm volatile("cp.async.commit_group;\n" ::: "memory")
#define CP_WAIT1()  asm volatile("cp.async.wait_group 1;\n" ::: "memory")
#define CP_WAIT0()  asm volatile("cp.async.wait_group 0;\n" ::: "memory")

// ------------------------- block reduction helper ----------------------------
__device__ __forceinline__ float bcastSum(float v) {
    __shared__ float sm[8];
    #pragma unroll
    for (int m = 16; m > 0; m >>= 1) v += __shfl_xor_sync(0xffffffffu, v, m);
    int w = threadIdx.x >> 5;
    if ((threadIdx.x & 31) == 0) sm[w] = v;
    __syncthreads();
    if (threadIdx.x < 8) {
        v = sm[threadIdx.x];
        #pragma unroll
        for (int m = 4; m > 0; m >>= 1) v += __shfl_xor_sync(0x000000ffu, v, m);
        if (threadIdx.x == 0) sm[0] = v;
    }
    __syncthreads();
    v = sm[0];
    __syncthreads();
    return v;
}

__device__ __forceinline__ void bcastSum4(float v[4]) {
    __shared__ float sm4[8][4];
    #pragma unroll
    for (int m = 16; m > 0; m >>= 1) {
        #pragma unroll
        for (int c = 0; c < 4; c++) v[c] += __shfl_xor_sync(0xffffffffu, v[c], m);
    }
    int w = threadIdx.x >> 5;
    if ((threadIdx.x & 31) == 0) {
        #pragma unroll
        for (int c = 0; c < 4; c++) sm4[w][c] = v[c];
    }
    __syncthreads();
    if (threadIdx.x < 8) {
        #pragma unroll
        for (int c = 0; c < 4; c++) v[c] = sm4[threadIdx.x][c];
        #pragma unroll
        for (int m = 4; m > 0; m >>= 1) {
            #pragma unroll
            for (int c = 0; c < 4; c++) v[c] += __shfl_xor_sync(0x000000ffu, v[c], m);
        }
        if (threadIdx.x == 0) {
            #pragma unroll
            for (int c = 0; c < 4; c++) sm4[0][c] = v[c];
        }
    }
    __syncthreads();
    #pragma unroll
    for (int c = 0; c < 4; c++) v[c] = sm4[0][c];
    __syncthreads();
}

// ---------- fused prep (B cols + params) AND lambda/x-pack ------------------
// grid = 3072 + 8192 = 11264 blocks, 256 threads.
// blocks [0,3072): prep of B column j; blocks [3072,11264): lam/x row r.
__global__ __launch_bounds__(256) void preplam_kernel(
    const float* __restrict__ zq, const float* __restrict__ bq,
    const float* __restrict__ zk, const float* __restrict__ bk,
    const float* __restrict__ wv, const float* __restrict__ x)
{
    int blk = blockIdx.x;
    int tid = threadIdx.x;
    if (blk >= N3) {
        // ---- lambda + bf16-scrambled x ----
        int r = blk - N3;
        float4 v = *(const float4*)(x + (size_t)r * DDm + tid * 4);
        float ss = v.x * v.x + v.y * v.y + v.z * v.z + v.w * v.w;
        uint32_t* row = g_Xb + (size_t)r * 512;
        uint32_t w0 = tid * 2;
        row[ph(w0)]     = pkbf(v.x, v.y);
        row[ph(w0 + 1)] = pkbf(v.z, v.w);
        ss = bcastSum(ss);
        if (tid == 0) g_lam[r] = 2.0f / (1.0f - ss);
        return;
    }
    int j = blk;
    int d0 = tid * 4;
    uint32_t w0 = tid * 2;
    if (j >= 2048) {
        int col = j - 2048;
        float4 v = *(const float4*)(wv + (size_t)col * DDm + d0);
        uint32_t* row = g_Bb + (size_t)j * 512;
        row[ph(w0)]     = pkbf(v.x, v.y);
        row[ph(w0 + 1)] = pkbf(v.z, v.w);
        return;
    }
    const float* z; const float* bias; int col;
    if (j < 1024) { z = zq; bias = bq; col = j; }
    else          { z = zk; bias = bk; col = j - 1024; }

    float vv[4];
    #pragma unroll
    for (int c = 0; c < 4; c++) vv[c] = z[(size_t)(d0 + c) * DDm + col];
    float ss = vv[0] * vv[0] + vv[1] * vv[1] + vv[2] * vv[2] + vv[3] * vv[3];
    ss = bcastSum(ss);
    float zn = fmaxf(sqrtf(ss), 1e-15f);
    float inv = 1.0f / zn;
    uint32_t* row = g_Bb + (size_t)j * 512;
    row[ph(w0)]     = pkbf(vv[0] * inv, vv[1] * inv);
    row[ph(w0 + 1)] = pkbf(vv[2] * inv, vv[3] * inv);
    if (tid == 0) {
        float r2 = 2.0f * bias[col];
        g_par[j] = make_float4(2.0f * zn, coshf(r2), sinhf(r2), 0.0f);
    }
}

// ------------------------- bf16 GEMM: g_INb = x @ B (m16n8k16) --------------
#define GAT 5120                          // words per [128][40] tile
__global__ __launch_bounds__(256, 2) void gemm_bf() {
    extern __shared__ uint32_t sm[];
    uint32_t sbase = (uint32_t)__cvta_generic_to_shared(sm);

    int tid = threadIdx.x;
    int warp = tid >> 5, lane = tid & 31;
    int g = lane >> 2, tig = lane & 3;
    int wm = warp >> 2, wn = warp & 3;
    int m0 = blockIdx.y * 128, n0 = blockIdx.x * 128;

    const uint32_t* Aw = g_Xb + (size_t)m0 * 512;
    const uint32_t* Bw = g_Bb + (size_t)n0 * 512;

    auto load_chunk = [&](int ch, int buf) {
        uint32_t dst = sbase + (uint32_t)(buf * 2 * GAT) * 4;
        #pragma unroll
        for (int i = 0; i < 8; i++) {
            int id = tid + i * 256;            // 0..2047
            int mat = id >> 10;                // 0:A 1:B
            int r = (id & 1023) >> 3;
            int o4 = (id & 7) * 4;
            uint32_t s = dst + (uint32_t)(mat * GAT + r * 40 + o4) * 4;
            const uint32_t* gp = (mat ? Bw : Aw) + (size_t)r * 512 + ch * 32 + o4;
            cpasync16(s, gp);
        }
        CP_COMMIT();
    };

    float acc[4][4][4];
    #pragma unroll
    for (int mi = 0; mi < 4; mi++)
        #pragma unroll
        for (int ni = 0; ni < 4; ni++)
            #pragma unroll
            for (int c = 0; c < 4; c++) acc[mi][ni][c] = 0.0f;

    load_chunk(0, 0);

    int buf = 0;
    for (int ch = 0; ch < 16; ch++) {
        if (ch + 1 < 16) {
            load_chunk(ch + 1, buf ^ 1);
            CP_WAIT1();
        } else {
            CP_WAIT0();
        }
        __syncthreads();
        const uint32_t* A = sm + buf * 2 * GAT;
        const uint32_t* B = A + GAT;

        #pragma unroll
        for (int ks = 0; ks < 4; ks++) {
            uint32_t af[4][4];
            #pragma unroll
            for (int mi = 0; mi < 4; mi++) {
                int r = wm * 64 + mi * 16;
                uint2 v = *(const uint2*)&A[(r + g)     * 40 + ks * 8 + 2 * tig];
                uint2 u = *(const uint2*)&A[(r + g + 8) * 40 + ks * 8 + 2 * tig];
                af[mi][0] = v.x; af[mi][1] = u.x; af[mi][2] = v.y; af[mi][3] = u.y;
            }
            uint2 bfv[4];
            #pragma unroll
            for (int ni = 0; ni < 4; ni++)
                bfv[ni] = *(const uint2*)&B[(wn * 32 + ni * 8 + g) * 40 + ks * 8 + 2 * tig];
            #pragma unroll
            for (int mi = 0; mi < 4; mi++)
                #pragma unroll
                for (int ni = 0; ni < 4; ni++)
                    mma_bf16(acc[mi][ni], af[mi], bfv[ni].x, bfv[ni].y);
        }
        __syncthreads();
        buf ^= 1;
    }

    // epilogue: pack fp32 accumulators to bf16x2 words
    #pragma unroll
    for (int mi = 0; mi < 4; mi++) {
        int mr = m0 + wm * 64 + mi * 16 + g;
        #pragma unroll
        for (int ni = 0; ni < 4; ni++) {
            int wc = (n0 + wn * 32 + ni * 8 + tig * 2) >> 1;
            g_INb[(size_t)mr * 1536 + wc]       = pkbf(acc[mi][ni][0], acc[mi][ni][1]);
            g_INb[(size_t)(mr + 8) * 1536 + wc] = pkbf(acc[mi][ni][2], acc[mi][ni][3]);
        }
    }
}

// ------------------------- colsum of V projection (packed reads) ------------
__global__ __launch_bounds__(256) void csum_kernel() {
    int bh = blockIdx.x;
    int c  = blockIdx.y;
    int b = bh >> 4, h = bh & 15;
    int t = threadIdx.x;
    int w = t & 31, sub = t >> 5;            // sub 0..7
    int srow0 = c * 512 + sub * 64;
    const uint32_t* base = g_INb + ((size_t)(b * 2048 + srow0)) * 1536 + 1024 + h * 32 + w;
    float sl = 0.f, sh = 0.f;
    for (int i = 0; i < 64; i++) {
        float2 v = upbf(base[(size_t)i * 1536]);
        sl += v.x; sh += v.y;
    }
    __shared__ float red[256][2];
    red[t][0] = sl; red[t][1] = sh;
    __syncthreads();
    if (t < 32) {
        float al = 0.f, ah = 0.f;
        #pragma unroll
        for (int s = 0; s < 8; s++) {
            al += red[s * 32 + t][0];
            ah += red[s * 32 + t][1];
        }
        g_cs4[(c * BHh + bh) * 64 + 2 * t]     = al;
        g_cs4[(c * BHh + bh) * 64 + 2 * t + 1] = ah;
    }
}

// ------------------------- epilogue: Poincare map -> bf16 layouts -----------
__global__ __launch_bounds__(256) void epi_kernel(const float* __restrict__ bvp) {
    int r0 = blockIdx.x * 4;
    int b  = r0 >> 11;
    int s0 = r0 & 2047;
    int tid = threadIdx.x;
    int j0 = tid * 4;
    int h  = j0 >> 6, dk = j0 & 63;
    int bh = b * 16 + h;

    float lamv[4];
    *(float4*)lamv = *(const float4*)(g_lam + r0);

    float wq[4][4];
    // ---------------- Q (scale log2e/8 for exp2-softmax) ----------------
    {
        float4 par[4];
        #pragma unroll
        for (int c = 0; c < 4; c++) par[c] = g_par[j0 + c];
        float ws[4] = {0.f, 0.f, 0.f, 0.f};
        #pragma unroll
        for (int ri = 0; ri < 4; ri++) {
            float lam = lamv[ri], lm1 = lam - 1.0f;
            uint2 iw = *(const uint2*)(g_INb + (size_t)(r0 + ri) * 1536 + tid * 2);
            float2 i0 = upbf(iw.x), i1 = upbf(iw.y);
            float innv[4] = {i0.x, i0.y, i1.x, i1.y};
            #pragma unroll
            for (int c = 0; c < 4; c++) {
                float arg = lam * innv[c] * par[c].y - lm1 * par[c].z;
                float t   = arg + sqrtf(arg * arg + 1.0f);
                float u   = par[c].x * __logf(t);
                float eu  = __expf(u);
                float w   = 0.5f * (eu - __fdividef(1.0f, eu));
                wq[ri][c] = w;
                ws[ri] += w * w;
            }
        }
        bcastSum4(ws);
        #pragma unroll
        for (int ri = 0; ri < 4; ri++) {
            float scl = 0.18033688f / (1.0f + sqrtf(1.0f + ws[ri]));  // log2(e)/8
            uint2 ov = make_uint2(pkbf(wq[ri][0] * scl, wq[ri][1] * scl),
                                  pkbf(wq[ri][2] * scl, wq[ri][3] * scl));
            *(uint2*)(g_Qb + ((size_t)bh * SS + s0 + ri) * 32 + (dk >> 1)) = ov;
        }
    }
    // ---------------- K (word-scrambled dk layout) ----------------
    {
        float4 par[4];
        #pragma unroll
        for (int c = 0; c < 4; c++) par[c] = g_par[1024 + j0 + c];
        float ws2[4] = {0.f, 0.f, 0.f, 0.f};
        #pragma unroll
        for (int ri = 0; ri < 4; ri++) {
            float lam = lamv[ri], lm1 = lam - 1.0f;
            uint2 iw = *(const uint2*)(g_INb + (size_t)(r0 + ri) * 1536 + 512 + tid * 2);
            float2 i0 = upbf(iw.x), i1 = upbf(iw.y);
            float innv[4] = {i0.x, i0.y, i1.x, i1.y};
            #pragma unroll
            for (int c = 0; c < 4; c++) {
                float arg = lam * innv[c] * par[c].y - lm1 * par[c].z;
                float t   = arg + sqrtf(arg * arg + 1.0f);
                float u   = par[c].x * __logf(t);
                float eu  = __expf(u);
                float w   = 0.5f * (eu - __fdividef(1.0f, eu));
                wq[ri][c] = w;
                ws2[ri] += w * w;
            }
        }
        bcastSum4(ws2);
        uint32_t wl0 = dk >> 1;
        uint32_t p0 = ph(wl0), p1 = ph(wl0 + 1);
        #pragma unroll
        for (int ri = 0; ri < 4; ri++) {
            float scl = 1.0f / (1.0f + sqrtf(1.0f + ws2[ri]));
            uint32_t* row = g_Kb + ((size_t)bh * SS + s0 + ri) * 32;
            row[p0] = pkbf(wq[ri][0] * scl, wq[ri][1] * scl);
            row[p1] = pkbf(wq[ri][2] * scl, wq[ri][3] * scl);
        }
    }
    // ---------------- V (transposed, word-scrambled s layout) ----------------
    {
        float4 bvv = *(const float4*)(bvp + j0);
        float vv[4][4];
        #pragma unroll
        for (int ri = 0; ri < 4; ri++) {
            uint2 iw = *(const uint2*)(g_INb + (size_t)(r0 + ri) * 1536 + 1024 + tid * 2);
            float2 i0 = upbf(iw.x), i1 = upbf(iw.y);
            vv[ri][0] = i0.x + bvv.x;
            vv[ri][1] = i0.y + bvv.y;
            vv[ri][2] = i1.x + bvv.z;
            vv[ri][3] = i1.y + bvv.w;
        }
        uint32_t wl0 = s0 >> 1;
        uint32_t ps0 = ph(wl0), ps1 = ph(wl0 + 1);
        #pragma unroll
        for (int c = 0; c < 4; c++) {
            uint32_t* row = g_Vb + ((size_t)bh * DKk + dk + c) * 1024;
            row[ps0] = pkbf(vv[0][c], vv[1][c]);
            row[ps1] = pkbf(vv[2][c], vv[3][c]);
        }
    }
}

// ------------------------- flash attention (bf16 m16n8k16, centered P) ------
// O = colsumV + sum_k (p_k - 1) v_k ; l = sum p_k.  (R14-proven config)
__global__ __launch_bounds__(256, 2) void attn_kernel(float* __restrict__ out,
                                                      const float* __restrict__ bvp) {
    extern __shared__ uint32_t usmem[];
    const int TW = 64 * 40;
    uint32_t sbase = (uint32_t)__cvta_generic_to_shared(usmem);

    int tid  = threadIdx.x;
    int warp = tid >> 5, lane = tid & 31;
    int g = lane >> 2, tig = lane & 3;
    int bh = blockIdx.y;
    int b  = bh >> 4, h = bh & 15;
    int q0 = blockIdx.x * 128;
    int wq = warp * 16;

    const uint32_t* Qw = g_Qb + ((size_t)bh * SS + q0 + wq) * 32;
    const uint32_t* Kw = g_Kb + (size_t)bh * SS * 32;
    const uint32_t* Vw = g_Vb + (size_t)bh * DKk * 1024;

    uint32_t qa[4][4];
    #pragma unroll
    for (int ktq = 0; ktq < 4; ktq++) {
        qa[ktq][0] = Qw[(size_t)g       * 32 + ktq * 8 + tig];
        qa[ktq][1] = Qw[(size_t)(g + 8) * 32 + ktq * 8 + tig];
        qa[ktq][2] = Qw[(size_t)g       * 32 + ktq * 8 + tig + 4];
        qa[ktq][3] = Qw[(size_t)(g + 8) * 32 + ktq * 8 + tig + 4];
    }

    float o[8][4];
    #pragma unroll
    for (int n = 0; n < 8; n++)
        #pragma unroll
        for (int c = 0; c < 4; c++) o[n][c] = 0.0f;
    float l0 = 0.0f, l1 = 0.0f;

    auto load_tile = [&](int buf, int it) {
        int kc0 = it * 64;
        uint32_t sk = sbase + (uint32_t)(buf * TW) * 4;
        uint32_t sv = sbase + (uint32_t)((2 + buf) * TW) * 4;
        #pragma unroll
        for (int i = 0; i < 2; i++) {
            int chunk = tid + i * 256;
            int row = chunk >> 3;
            int off = (chunk & 7) * 4;
            cpasync16(sk + (uint32_t)(row * 40 + off) * 4,
                      Kw + (size_t)(kc0 + row) * 32 + off);
            cpasync16(sv + (uint32_t)(row * 40 + off) * 4,
                      Vw + (size_t)row * 1024 + it * 32 + off);
        }
        CP_COMMIT();
    };

    load_tile(0, 0);

    int buf = 0;
    for (int it = 0; it < SS / 64; it++) {
        if (it + 1 < SS / 64) {
            load_tile(buf ^ 1, it + 1);
            CP_WAIT1();
        } else {
            CP_WAIT0();
        }
        __syncthreads();
        const uint32_t* sK = usmem + buf * TW;
        const uint32_t* sV = usmem + (2 + buf) * TW;

        float p[8][4];
        #pragma unroll
        for (int n = 0; n < 8; n++)
            #pragma unroll
            for (int c = 0; c < 4; c++) p[n][c] = 0.0f;
        #pragma unroll
        for (int ktq = 0; ktq < 4; ktq++) {
            #pragma unroll
            for (int n0 = 0; n0 < 8; n0++) {
                uint2 kb = *(const uint2*)(sK + (n0 * 8 + g) * 40 + ktq * 8 + 2 * tig);
                mma_bf16(p[n0], qa[ktq], kb.x, kb.y);
            }
        }

        #pragma unroll
        for (int n = 0; n < 8; n++) {
            float e0 = fex2(p[n][0]);
            float e1 = fex2(p[n][1]);
            float e2 = fex2(p[n][2]);
            float e3 = fex2(p[n][3]);
            l0 += e0 + e1;
            l1 += e2 + e3;
            p[n][0] = e0 - 1.0f;
            p[n][1] = e1 - 1.0f;
            p[n][2] = e2 - 1.0f;
            p[n][3] = e3 - 1.0f;
        }

        uint32_t pa[4][4];
        #pragma unroll
        for (int ktp = 0; ktp < 4; ktp++) {
            pa[ktp][0] = pkbf(p[2 * ktp    ][0], p[2 * ktp    ][1]);
            pa[ktp][1] = pkbf(p[2 * ktp    ][2], p[2 * ktp    ][3]);
            pa[ktp][2] = pkbf(p[2 * ktp + 1][0], p[2 * ktp + 1][1]);
            pa[ktp][3] = pkbf(p[2 * ktp + 1][2], p[2 * ktp + 1][3]);
        }

        #pragma unroll
        for (int ktp = 0; ktp < 4; ktp++) {
            #pragma unroll
            for (int n0 = 0; n0 < 8; n0++) {
                uint2 vb = *(const uint2*)(sV + (n0 * 8 + g) * 40 + ktp * 8 + 2 * tig);
                mma_bf16(o[n0], pa[ktp], vb.x, vb.y);
            }
        }
        __syncthreads();
        buf ^= 1;
    }

    l0 += __shfl_xor_sync(0xffffffffu, l0, 1);
    l0 += __shfl_xor_sync(0xffffffffu, l0, 2);
    l1 += __shfl_xor_sync(0xffffffffu, l1, 1);
    l1 += __shfl_xor_sync(0xffffffffu, l1, 2);

    float inv0 = 1.0f / l0, inv1 = 1.0f / l1;
    int s0r = q0 + wq + g;
    #pragma unroll
    for (int n0 = 0; n0 < 8; n0++) {
        int dk = n0 * 8 + 2 * tig;
        float csx = 0.0f, csy = 0.0f;
        #pragma unroll
        for (int c = 0; c < 4; c++) {
            float2 t = *(const float2*)(g_cs4 + ((size_t)(c * BHh + bh)) * 64 + dk);
            csx += t.x; csy += t.y;
        }
        float2 bv2 = *(const float2*)(bvp + h * 64 + dk);
        csx += 2048.0f * bv2.x;
        csy += 2048.0f * bv2.y;
        float2 ov0 = make_float2((csx + o[n0][0]) * inv0, (csy + o[n0][1]) * inv0);
        float2 ov1 = make_float2((csx + o[n0][2]) * inv1, (csy + o[n0][3]) * inv1);
        *(float2*)(out + ((size_t)(b * SS + s0r)     ) * DDm + h * 64 + dk) = ov0;
        *(float2*)(out + ((size_t)(b * SS + s0r + 8) ) * DDm + h * 64 + dk) = ov1;
    }
}

// ------------------------- launcher ----------------------------------------
extern "C" void kernel_launch(void* const* d_in, const int* in_sizes, int n_in,
                              void* d_out, int out_size) {
    const float* x  = (const float*)d_in[0];
    const float* zq = (const float*)d_in[1];
    const float* bq = (const float*)d_in[2];
    const float* zk = (const float*)d_in[3];
    const float* bk = (const float*)d_in[4];
    const float* wv = (const float*)d_in[5];
    const float* bv = (const float*)d_in[6];
    float* out = (float*)d_out;

    preplam_kernel<<<N3 + BSr, 256>>>(zq, bq, zk, bk, wv, x);

    int gsmem = 2 * 2 * GAT * 4;   // 81920
    cudaFuncSetAttribute(gemm_bf, cudaFuncAttributeMaxDynamicSharedMemorySize, gsmem);
    gemm_bf<<<dim3(N3 / 128, BSr / 128), 256, gsmem>>>();

    csum_kernel<<<dim3(BHh, 4), 256>>>();
    epi_kernel<<<BSr / 4, 256>>>(bv);

    int smem_bytes = 4 * 64 * 40 * 4;   // 40960 (2-stage, R14 config)
    cudaFuncSetAttribute(attn_kernel, cudaFuncAttributeMaxDynamicSharedMemorySize, smem_bytes);
    attn_kernel<<<dim3(SS / 128, BHh), 256, smem_bytes>>>(out, bv);
}